// round 13
// baseline (speedup 1.0000x reference)
#include <cuda_runtime.h>
#include <math.h>

// Problem constants
#define BB 4
#define SS 256
#define NN 512
#define RR 32
#define LL (NN * RR)          // 16384 output samples per batch
#define NCHUNK 8
#define S_PER_CHUNK (SS / NCHUNK)  // 32
#define NE 513                // extended segments: head(1) + 511 mids + tail
#define NQ2 257               // ceil(513/2) segment-pairs per batch
#define NPAIR (BB * NQ2)      // 1028 synthesis work units
#define NSEQ (BB * SS)        // 1024 scan sequences
#define NWRK 592              // 4 x 148 SMs; all co-resident at occ>=4

// Reference-matching constants
#define TWO_PI_D 6.283185307179586
#define CF_F  ((float)(TWO_PI_D / 44100.0))
#define CMOD_F ((float)TWO_PI_D)
#define INV_CMOD_F ((float)(1.0 / (double)((float)TWO_PI_D)))

// Scratch — [seq][e] layout (phase-1 writes coalesced along e per seq-row)
__device__ float4 d_tab[NSEQ * NE];          // {base_mod, g, dg/64, a}
__device__ float  d_da [NSEQ * NE];          // a_{i+1}-a_i

// Software grid barrier state (zero-initialized; self-resetting per replay)
__device__ volatile int d_bar0;
__device__ int d_bar1;

// ---------------------------------------------------------------------------
// double-float helpers (all-fp32 compensated arithmetic)
// ---------------------------------------------------------------------------
__device__ __forceinline__ float2 two_sum(float a, float b) {
    float s  = a + b;
    float bb = s - a;
    float e  = (a - (s - bb)) + (b - bb);
    return make_float2(s, e);
}
__device__ __forceinline__ float2 df_add(float2 a, float2 b) {
    float2 s = two_sum(a.x, b.x);
    float lo = s.y + (a.y + b.y);
    float hi = s.x + lo;
    lo = lo - (hi - s.x);
    return make_float2(hi, lo);
}

// ---------------------------------------------------------------------------
// Fused kernel: phase 1 (df prefix scan -> segment table) + software grid
// barrier + phase 2 (synthesis with SMEM-staged table). One launch: pays the
// per-kernel ramp overhead once instead of twice.
// ---------------------------------------------------------------------------
__global__ void __launch_bounds__(256, 4) k_fused(const float* __restrict__ freq,
                                                  const float* __restrict__ amp,
                                                  float* __restrict__ out) {
    int tid  = threadIdx.x;
    int lane = tid & 31;
    int wid  = tid >> 5;

    __shared__ float2 wsum[8];
    __shared__ float4 stab[SS][2];      // phase-2 staged table (8 KB)
    __shared__ float  sda [SS][2];      // 2 KB
    __shared__ float  sred[NCHUNK][2 * 33];

    // ================= PHASE 1: control-point scan =================
    // 256 threads handle 512 control points: thread t owns i0=2t, i1=2t+1.
    for (int seq = blockIdx.x; seq < NSEQ; seq += NWRK) {
        int i0 = 2 * tid, i1 = i0 + 1;
        float f0 = freq[seq * NN + i0];
        float f1 = freq[seq * NN + i1];
        float a0 = amp [seq * NN + i0];
        float a1 = amp [seq * NN + i1];

        float g0h = f0 * CF_F, g0l = fmaf(f0, CF_F, -g0h);
        float g1h = f1 * CF_F, g1l = fmaf(f1, CF_F, -g1h);
        float2 g0 = make_float2(g0h, g0l);
        float2 g1 = make_float2(g1h, g1l);
        float2 pr = df_add(g0, g1);          // per-thread pair sum

        // warp inclusive scan of pair sums (df)
        float2 x = pr;
        #pragma unroll
        for (int off = 1; off < 32; off <<= 1) {
            float yh = __shfl_up_sync(0xFFFFFFFFu, x.x, off);
            float yl = __shfl_up_sync(0xFFFFFFFFu, x.y, off);
            if (lane >= off) x = df_add(x, make_float2(yh, yl));
        }
        if (lane == 31) wsum[wid] = x;
        __syncthreads();
        if (wid == 0) {
            float2 y = (lane < 8) ? wsum[lane] : make_float2(0.0f, 0.0f);
            #pragma unroll
            for (int off = 1; off < 8; off <<= 1) {
                float zh = __shfl_up_sync(0xFFFFFFFFu, y.x, off);
                float zl = __shfl_up_sync(0xFFFFFFFFu, y.y, off);
                if (lane >= off) y = df_add(y, make_float2(zh, zl));
            }
            if (lane < 8) wsum[lane] = y;
        }
        __syncthreads();

        // thread-exclusive prefix of pair sums
        float xh = __shfl_up_sync(0xFFFFFFFFu, x.x, 1);
        float xl = __shfl_up_sync(0xFFFFFFFFu, x.y, 1);
        float2 excl = (lane == 0) ? make_float2(0.0f, 0.0f) : make_float2(xh, xl);
        if (wid > 0) excl = df_add(excl, wsum[wid - 1]);

        float2 Q0 = df_add(excl, g0);        // inclusive prefix at i0
        float2 Q1 = df_add(Q0, g1);          // inclusive prefix at i1

        size_t tb = (size_t)seq * NE;

        // entry for i0 (fnext = f1, anext = a1, both in-register)
        {
            float2 P = df_add(make_float2(32.0f * Q0.x, 32.0f * Q0.y),
                              make_float2(-16.0f * g0.x, -16.0f * g0.y));
            float qq = floorf(P.x * INV_CMOD_F);
            float m  = fmaf(-qq, CMOD_F, P.x) + P.y;
            float dg64 = (g1h - g0h) * (1.0f / 64.0f);
            float da   = a1 - a0;
            d_tab[tb + i0 + 1] = make_float4(m, g0h, dg64, a0);
            d_da [tb + i0 + 1] = da;
            if (i0 == 0) {                   // head segment e=0
                d_tab[tb] = make_float4(0.0f, g0h, 0.0f, a0);
                d_da [tb] = 0.0f;
            }
        }
        // entry for i1 (needs f[i1+1], a[i1+1] unless last)
        {
            float fn = (i1 < NN - 1) ? freq[seq * NN + i1 + 1] : f1;
            float an = (i1 < NN - 1) ? amp [seq * NN + i1 + 1] : a1;
            float2 P = df_add(make_float2(32.0f * Q1.x, 32.0f * Q1.y),
                              make_float2(-16.0f * g1.x, -16.0f * g1.y));
            float qq = floorf(P.x * INV_CMOD_F);
            float m  = fmaf(-qq, CMOD_F, P.x) + P.y;
            float dg64 = (i1 < NN - 1) ? (fn * CF_F - g1h) * (1.0f / 64.0f) : 0.0f;
            float da   = (i1 < NN - 1) ? (an - a1) : 0.0f;
            d_tab[tb + i1 + 1] = make_float4(m, g1h, dg64, a1);
            d_da [tb + i1 + 1] = da;
        }
        __syncthreads();   // protect wsum reuse next iteration
    }

    // ================= GRID BARRIER (all 592 blocks co-resident) ===========
    __syncthreads();
    if (tid == 0) {
        __threadfence();                       // flush table writes
        atomicAdd((int*)&d_bar0, 1);
        while (d_bar0 < NWRK) { __nanosleep(64); }
    }
    __syncthreads();

    // ================= PHASE 2: synthesis ==================================
    int c    = tid >> 5;            // sine chunk 0..7
    int seg2 = lane >> 4;           // local segment 0..1
    int jg   = lane & 15;           // samples j = jg, jg+16

    float u0 = (float)(jg + 1);
    float u1 = u0 + 16.0f;
    float s0 = u0 * u0, s1 = u1 * u1;
    float w0 = (float)(2 * jg + 1) * (1.0f / 64.0f);
    float w1 = w0 + 0.5f;

    for (int p = blockIdx.x; p < NPAIR; p += NWRK) {
        int q = p % NQ2;            // segment pair
        int b = p / NQ2;
        int e0  = 2 * q;
        int e0c = (e0     > NE - 1) ? (NE - 1) : e0;
        int e1c = (e0 + 1 > NE - 1) ? (NE - 1) : (e0 + 1);

        // stage the pair's table slice: 256 sines x 2 segments
        {
            const float4* row  = d_tab + (size_t)(b * SS + tid) * NE;
            const float*  drow = d_da  + (size_t)(b * SS + tid) * NE;
            stab[tid][0] = __ldg(row  + e0c);
            stab[tid][1] = __ldg(row  + e1c);
            sda [tid][0] = __ldg(drow + e0c);
            sda [tid][1] = __ldg(drow + e1c);
        }
        __syncthreads();

        int sbase = c * S_PER_CHUNK;
        float a0 = 0.0f, a1 = 0.0f;

        #pragma unroll
        for (int k = 0; k < S_PER_CHUNK; k += 4) {
            float4 v0 = stab[sbase + k    ][seg2];
            float4 v1 = stab[sbase + k + 1][seg2];
            float4 v2 = stab[sbase + k + 2][seg2];
            float4 v3 = stab[sbase + k + 3][seg2];
            float  d0 = sda [sbase + k    ][seg2];
            float  d1 = sda [sbase + k + 1][seg2];
            float  d2 = sda [sbase + k + 2][seg2];
            float  d3 = sda [sbase + k + 3][seg2];

            float p00 = fmaf(s0, v0.z, fmaf(u0, v0.y, v0.x));
            float p01 = fmaf(s1, v0.z, fmaf(u1, v0.y, v0.x));
            float p10 = fmaf(s0, v1.z, fmaf(u0, v1.y, v1.x));
            float p11 = fmaf(s1, v1.z, fmaf(u1, v1.y, v1.x));
            float p20 = fmaf(s0, v2.z, fmaf(u0, v2.y, v2.x));
            float p21 = fmaf(s1, v2.z, fmaf(u1, v2.y, v2.x));
            float p30 = fmaf(s0, v3.z, fmaf(u0, v3.y, v3.x));
            float p31 = fmaf(s1, v3.z, fmaf(u1, v3.y, v3.x));

            float m00 = fmaf(w0, d0, v0.w);
            float m01 = fmaf(w1, d0, v0.w);
            float m10 = fmaf(w0, d1, v1.w);
            float m11 = fmaf(w1, d1, v1.w);
            float m20 = fmaf(w0, d2, v2.w);
            float m21 = fmaf(w1, d2, v2.w);
            float m30 = fmaf(w0, d3, v3.w);
            float m31 = fmaf(w1, d3, v3.w);

            a0 = fmaf(m00, __sinf(p00), a0);
            a1 = fmaf(m01, __sinf(p01), a1);
            a0 = fmaf(m10, __sinf(p10), a0);
            a1 = fmaf(m11, __sinf(p11), a1);
            a0 = fmaf(m20, __sinf(p20), a0);
            a1 = fmaf(m21, __sinf(p21), a1);
            a0 = fmaf(m30, __sinf(p30), a0);
            a1 = fmaf(m31, __sinf(p31), a1);
        }

        int base = seg2 * 33 + jg;
        sred[c][base     ] = a0;
        sred[c][base + 16] = a1;
        __syncthreads();

        if (tid < 64) {
            int e_loc = tid >> 5;           // 0..1
            int j     = tid & 31;
            int e_out = 2 * q + e_loc;
            float s = 0.0f;
            #pragma unroll
            for (int cc = 0; cc < NCHUNK; cc++) s += sred[cc][e_loc * 33 + j];

            bool valid = (e_out <= NE - 1);
            if (e_out == 0 || e_out == NE - 1) valid = valid && (j < 16);
            if (valid) {
                int t = (e_out == 0) ? j : 16 + 32 * (e_out - 1) + j;
                out[b * LL + t] = s;
            }
        }
        __syncthreads();   // separate sred reads from next iteration's writes
    }

    // ================= BARRIER RESET (replay-safe) =========================
    __syncthreads();
    if (tid == 0) {
        __threadfence();
        int t = atomicAdd(&d_bar1, 1);
        if (t == NWRK - 1) {       // last block resets for the next replay
            d_bar0 = 0;
            d_bar1 = 0;
        }
    }
}

// ---------------------------------------------------------------------------
extern "C" void kernel_launch(void* const* d_in, const int* in_sizes, int n_in,
                              void* d_out, int out_size) {
    const float* freq = (const float*)d_in[0];
    const float* amp  = (const float*)d_in[1];
    float* out = (float*)d_out;

    k_fused<<<NWRK, 256>>>(freq, amp, out);    // single launch, one wave
}

// round 14
// speedup vs baseline: 1.2159x; 1.2159x over previous
#include <cuda_runtime.h>
#include <math.h>

// Problem constants
#define BB 4
#define SS 256
#define NN 512
#define RR 32
#define LL (NN * RR)          // 16384 output samples per batch
#define NCHUNK 8
#define S_PER_CHUNK (SS / NCHUNK)  // 32
#define NE 513                // extended segments: head(1) + 511 mids + tail
#define NQ2 257               // ceil(513/2) segment-pairs per batch

// Reference-matching constants
#define TWO_PI_D 6.283185307179586
#define CF_F  ((float)(TWO_PI_D / 44100.0))
#define CMOD_F ((float)TWO_PI_D)
#define INV_CMOD_F ((float)(1.0 / (double)((float)TWO_PI_D)))

// Scratch — [seq][e] layout (k_base writes coalesced; proven best in R9)
__device__ float4 d_tab[BB * SS * NE];       // {base_mod, g, dg/64, a}
__device__ float  d_da [BB * SS * NE];       // a_{i+1}-a_i

// ---------------------------------------------------------------------------
// double-float helpers (all-fp32 compensated arithmetic)
// ---------------------------------------------------------------------------
__device__ __forceinline__ float2 two_sum(float a, float b) {
    float s  = a + b;
    float bb = s - a;
    float e  = (a - (s - bb)) + (b - bb);
    return make_float2(s, e);
}
__device__ __forceinline__ float2 df_add(float2 a, float2 b) {
    float2 s = two_sum(a.x, b.x);
    float lo = s.y + (a.y + b.y);
    float hi = s.x + lo;
    lo = lo - (hi - s.x);
    return make_float2(hi, lo);
}

// ---------------------------------------------------------------------------
// Kernel 1: df-precision prefix of omegas -> per-segment fp32 table,
// [seq][e] layout (coalesced writes). Base phase reduced mod fl32(2*pi):
// hot-loop phase stays in [0,~30), where MUFU.SIN's HW range reduction
// adds only ~4e-6 rad of error.
// ---------------------------------------------------------------------------
__global__ void k_base(const float* __restrict__ freq,
                       const float* __restrict__ amp) {
    int seq  = blockIdx.x;
    int i    = threadIdx.x;
    int lane = i & 31;
    int wid  = i >> 5;

    float f = freq[seq * NN + i];
    float a = amp [seq * NN + i];

    float g_hi = f * CF_F;
    float g_lo = fmaf(f, CF_F, -g_hi);      // exact product tail
    float2 x = make_float2(g_hi, g_lo);

    #pragma unroll
    for (int off = 1; off < 32; off <<= 1) {
        float yh = __shfl_up_sync(0xFFFFFFFFu, x.x, off);
        float yl = __shfl_up_sync(0xFFFFFFFFu, x.y, off);
        if (lane >= off) x = df_add(x, make_float2(yh, yl));
    }

    __shared__ float2 wsum[16];
    if (lane == 31) wsum[wid] = x;
    __syncthreads();
    if (wid == 0) {
        float2 y = (lane < 16) ? wsum[lane] : make_float2(0.0f, 0.0f);
        #pragma unroll
        for (int off = 1; off < 16; off <<= 1) {
            float zh = __shfl_up_sync(0xFFFFFFFFu, y.x, off);
            float zl = __shfl_up_sync(0xFFFFFFFFu, y.y, off);
            if (lane >= off) y = df_add(y, make_float2(zh, zl));
        }
        if (lane < 16) wsum[lane] = y;
    }
    __syncthreads();
    float2 Q = x;
    if (wid > 0) Q = df_add(Q, wsum[wid - 1]);

    float2 Q32  = make_float2(32.0f * Q.x, 32.0f * Q.y);
    float2 g16n = make_float2(-16.0f * g_hi, -16.0f * g_lo);
    float2 P = df_add(Q32, g16n);

    float q = floorf(P.x * INV_CMOD_F);
    float m = fmaf(-q, CMOD_F, P.x) + P.y;

    float fnext = (i < NN - 1) ? freq[seq * NN + i + 1] : f;
    float anext = (i < NN - 1) ? amp [seq * NN + i + 1] : a;
    float dg64 = (i < NN - 1) ? (fnext * CF_F - g_hi) * (1.0f / 64.0f) : 0.0f;
    float da   = (i < NN - 1) ? (anext - a) : 0.0f;

    size_t tb = (size_t)seq * NE;
    d_tab[tb + i + 1] = make_float4(m, g_hi, dg64, a);
    d_da [tb + i + 1] = da;
    if (i == 0) {
        d_tab[tb] = make_float4(0.0f, g_hi, 0.0f, a);
        d_da [tb] = 0.0f;
    }
}

// ---------------------------------------------------------------------------
// Kernel 2 (R9 structure): synthesis with SMEM-staged table.
// Block = one (batch, segment-pair) x 256 sines. The 10KB slice {tab, da}
// is staged once; the fully-unrolled 32-sine loop runs out of LDS.
// Change vs R9: sda is read back as float4 groups-of-4 sines, replacing
// 4 LDS.32 with 1 LDS.128 per sine-batch (~10% fewer loop instructions).
// Fixed-order smem reduction => bitwise deterministic, same order as R9.
// ---------------------------------------------------------------------------
__global__ void __launch_bounds__(256, 4) k_main(float* __restrict__ out) {
    int tid  = threadIdx.x;
    int c    = tid >> 5;            // sine chunk 0..7
    int lane = tid & 31;
    int seg2 = lane >> 4;           // local segment 0..1
    int jg   = lane & 15;           // samples j = jg, jg+16

    int q = blockIdx.x % NQ2;       // segment pair
    int b = blockIdx.x / NQ2;
    int e0  = 2 * q;
    int e0c = (e0     > NE - 1) ? (NE - 1) : e0;
    int e1c = (e0 + 1 > NE - 1) ? (NE - 1) : (e0 + 1);

    // ---- stage the block's table slice: 256 sines x 2 segments ----
    __shared__ float4 stab[SS][2];      // 8 KB
    __shared__ float  sdaA[2][SS];      // 2 KB, [segment][sine] (float4-readable)
    {
        const float4* row  = d_tab + (size_t)(b * SS + tid) * NE;
        const float*  drow = d_da  + (size_t)(b * SS + tid) * NE;
        stab[tid][0] = __ldg(row  + e0c);
        stab[tid][1] = __ldg(row  + e1c);
        sdaA[0][tid] = __ldg(drow + e0c);
        sdaA[1][tid] = __ldg(drow + e1c);
    }
    __syncthreads();

    float u0 = (float)(jg + 1);
    float u1 = u0 + 16.0f;
    float s0 = u0 * u0, s1 = u1 * u1;
    float w0 = (float)(2 * jg + 1) * (1.0f / 64.0f);
    float w1 = w0 + 0.5f;

    int sbase = c * S_PER_CHUNK;
    const float4* daV = (const float4*)&sdaA[seg2][sbase];  // 16B-aligned
    float a0 = 0.0f, a1 = 0.0f;

    #pragma unroll
    for (int k = 0; k < S_PER_CHUNK; k += 4) {
        float4 v0 = stab[sbase + k    ][seg2];
        float4 v1 = stab[sbase + k + 1][seg2];
        float4 v2 = stab[sbase + k + 2][seg2];
        float4 v3 = stab[sbase + k + 3][seg2];
        float4 dv = daV[k >> 2];        // {da_k, da_k+1, da_k+2, da_k+3}

        float p00 = fmaf(s0, v0.z, fmaf(u0, v0.y, v0.x));
        float p01 = fmaf(s1, v0.z, fmaf(u1, v0.y, v0.x));
        float p10 = fmaf(s0, v1.z, fmaf(u0, v1.y, v1.x));
        float p11 = fmaf(s1, v1.z, fmaf(u1, v1.y, v1.x));
        float p20 = fmaf(s0, v2.z, fmaf(u0, v2.y, v2.x));
        float p21 = fmaf(s1, v2.z, fmaf(u1, v2.y, v2.x));
        float p30 = fmaf(s0, v3.z, fmaf(u0, v3.y, v3.x));
        float p31 = fmaf(s1, v3.z, fmaf(u1, v3.y, v3.x));

        float m00 = fmaf(w0, dv.x, v0.w);
        float m01 = fmaf(w1, dv.x, v0.w);
        float m10 = fmaf(w0, dv.y, v1.w);
        float m11 = fmaf(w1, dv.y, v1.w);
        float m20 = fmaf(w0, dv.z, v2.w);
        float m21 = fmaf(w1, dv.z, v2.w);
        float m30 = fmaf(w0, dv.w, v3.w);
        float m31 = fmaf(w1, dv.w, v3.w);

        a0 = fmaf(m00, __sinf(p00), a0);
        a1 = fmaf(m01, __sinf(p01), a1);
        a0 = fmaf(m10, __sinf(p10), a0);
        a1 = fmaf(m11, __sinf(p11), a1);
        a0 = fmaf(m20, __sinf(p20), a0);
        a1 = fmaf(m21, __sinf(p21), a1);
        a0 = fmaf(m30, __sinf(p30), a0);
        a1 = fmaf(m31, __sinf(p31), a1);
    }

    __shared__ float sred[NCHUNK][2 * 33];
    int base = seg2 * 33 + jg;
    sred[c][base     ] = a0;
    sred[c][base + 16] = a1;
    __syncthreads();

    if (tid < 64) {
        int e_loc = tid >> 5;           // 0..1
        int j     = tid & 31;
        int e_out = 2 * q + e_loc;
        float s = 0.0f;
        #pragma unroll
        for (int cc = 0; cc < NCHUNK; cc++) s += sred[cc][e_loc * 33 + j];

        bool valid = (e_out <= NE - 1);
        if (e_out == 0 || e_out == NE - 1) valid = valid && (j < 16);
        if (valid) {
            int t = (e_out == 0) ? j : 16 + 32 * (e_out - 1) + j;
            out[b * LL + t] = s;
        }
    }
}

// ---------------------------------------------------------------------------
extern "C" void kernel_launch(void* const* d_in, const int* in_sizes, int n_in,
                              void* d_out, int out_size) {
    const float* freq = (const float*)d_in[0];
    const float* amp  = (const float*)d_in[1];
    float* out = (float*)d_out;

    k_base<<<BB * SS, NN>>>(freq, amp);        // 1024 blocks x 512
    k_main<<<BB * NQ2, 256>>>(out);            // 1028 blocks x 256
}